// round 14
// baseline (speedup 1.0000x reference)
#include <cuda_runtime.h>
#include <cstdint>

// FWHT N=4096 fp32 — TWO rows per 256-thread CTA, packed as f32x2.
// Each butterfly is one add.rn.f32x2 / fma.rn.f32x2 (both rows at once);
// smem exchanges carry both rows per LDS.64/STS.64/STS.128; address ALU
// shared between rows. R14: __launch_bounds__(256,5) -> 40 warps/SM,
// 10 rows in flight per SM (R10 was occ4 / ~29 warps: warp-count-limited).
//
// 12 stages, 3 register rounds (proven bit mapping):
//   round 1: bits {0,1,7,8}   lane-contiguous LDG.128 per row
//   round 2: bits {2,3,4,5}   swizzled smem exchange (LDS.64/STS.64)
//   round 3: bits {6,9,10,11} swizzled LDS.64; coalesced scalar STG per row
// Pair-space swizzle: granule ps (16B), ps' = ps ^ ((ps>>4)&7) — verified
// conflict-free for all four access patterns. Output scaled by 2^-6.

#define HN       4096
#define NTHREADS 256
#define RPT      16

typedef unsigned long long ull;

#define PACK2(out, lo, hi) \
    asm("mov.b64 %0, {%1, %2};" : "=l"(out) : "f"(lo), "f"(hi))
#define UNPACK2(lo, hi, in) \
    asm("mov.b64 {%0, %1}, %2;" : "=f"(lo), "=f"(hi) : "l"(in))
#define ADD2(out, a, b) \
    asm("add.rn.f32x2 %0, %1, %2;" : "=l"(out) : "l"(a), "l"(b))
#define SUB2(out, a, b, negone) \
    asm("fma.rn.f32x2 %0, %1, %2, %3;" : "=l"(out) : "l"(b), "l"(negone), "l"(a))
#define MUL2(out, a, b) \
    asm("mul.rn.f32x2 %0, %1, %2;" : "=l"(out) : "l"(a), "l"(b))

#define BFLY(i, j)  do { ull _a = V[i], _b = V[j]; \
                         ADD2(V[i], _a, _b); SUB2(V[j], _a, _b, NEG1); } while (0)

#define BUTTERFLY_ALL()                                   \
    _Pragma("unroll")                                     \
    for (int st = 1; st < RPT; st <<= 1) {                \
        _Pragma("unroll")                                 \
        for (int i = 0; i < RPT; i++)                     \
            if (!(i & st)) BFLY(i, i ^ st);               \
    }

__global__ __launch_bounds__(NTHREADS, 5)
void fwht2_kernel(const float* __restrict__ X, float* __restrict__ Y)
{
    __shared__ ull s8[HN];                     // 4096 row-pairs, 32 KB
    char* const sb = reinterpret_cast<char*>(s8);

    const size_t rp = blockIdx.x;              // row-pair index
    const float* __restrict__ x0 = X + rp * (2 * HN);
    float*       __restrict__ y0 = Y + rp * (2 * HN);

    const int t = threadIdx.x;
    const int w = t >> 5;          // warp 0..7
    const int l = t & 31;          // lane

    const ull NEG1 = 0xBF800000BF800000ULL;    // (-1.0f, -1.0f)

    ull V[RPT];

    // ---- Round 1 load: float4 slot qs = w*128 + j*32 + l from BOTH rows ----
    {
        const float4* __restrict__ xv0 = reinterpret_cast<const float4*>(x0);
        const float4* __restrict__ xv1 = xv0 + (HN / 4);
        #pragma unroll
        for (int j = 0; j < 4; j++) {
            int qs = w * 128 + j * 32 + l;
            float4 a = xv0[qs];
            float4 b = xv1[qs];
            PACK2(V[4*j+0], a.x, b.x);
            PACK2(V[4*j+1], a.y, b.y);
            PACK2(V[4*j+2], a.z, b.z);
            PACK2(V[4*j+3], a.w, b.w);
        }
    }
    // reg r = j*4+k : bits r0,r1 = n0,n1 ; r2,r3 = n7,n8
    BUTTERFLY_ALL();

    // ---- Exchange 1 write: granule ps = 2*qs + h, swizzled; STS.128 ----
    #pragma unroll
    for (int j = 0; j < 4; j++) {
        int qs = w * 128 + j * 32 + l;
        #pragma unroll
        for (int h = 0; h < 2; h++) {
            int ps = 2 * qs + h;
            int sw = ps ^ ((ps >> 4) & 7);
            ulonglong2 pk;
            pk.x = V[4*j + 2*h];
            pk.y = V[4*j + 2*h + 1];
            *reinterpret_cast<ulonglong2*>(sb + sw * 16) = pk;
        }
    }
    __syncthreads();

    // ---- Round 2: fixed p=n0n1, q=n6, u=n7n8, w=n9..11 ; i = n2..5 ----
    const int p  = l & 3;
    const int q  = (l >> 2) & 1;
    const int u  = (l >> 3) & 3;
    const int base2 = (p >> 1) + 32 * q + 64 * u + 256 * w;   // granule base
    const int off8  = (p & 1) * 8;
    #pragma unroll
    for (int i = 0; i < RPT; i++) {
        int ps = base2 + 2 * i;
        int sw = ps ^ ((ps >> 4) & 7);
        V[i] = *reinterpret_cast<const ull*>(sb + sw * 16 + off8);  // LDS.64
    }
    BUTTERFLY_ALL();
    #pragma unroll
    for (int i = 0; i < RPT; i++) {
        int ps = base2 + 2 * i;
        int sw = ps ^ ((ps >> 4) & 7);
        *reinterpret_cast<ull*>(sb + sw * 16 + off8) = V[i];        // STS.64
    }
    __syncthreads();

    // ---- Round 3: fixed m = n0..5, u2 = n7n8 ; i2 -> {n6, n9,n10,n11} ----
    const int u2 = w >> 1;
    const int m  = ((w & 1) << 5) | l;
    const int base3 = (m >> 1) + 64 * u2;        // + 32*b6 + 256*hi
    const int off3  = (m & 1) * 8;
    #pragma unroll
    for (int i2 = 0; i2 < RPT; i2++) {
        int b6 = i2 & 1, hi = i2 >> 1;
        int ps = base3 + 32 * b6 + 256 * hi;
        int sw = ps ^ ((ps >> 4) & 7);
        V[i2] = *reinterpret_cast<const ull*>(sb + sw * 16 + off3);  // LDS.64
    }
    BUTTERFLY_ALL();

    // ---- Scale by 2^-6, unpack, store both rows (coalesced per row) ----
    const ull SCALE = 0x3C8000003C800000ULL;     // (2^-6, 2^-6)
    float* __restrict__ y1 = y0 + HN;
    const int obase = m + 128 * u2;
    #pragma unroll
    for (int i2 = 0; i2 < RPT; i2++) {
        int b6 = i2 & 1, hi = i2 >> 1;
        int n  = obase + 64 * b6 + 512 * hi;
        ull sc; MUL2(sc, V[i2], SCALE);
        float r0, r1; UNPACK2(r0, r1, sc);
        __stcs(&y0[n], r0);
        __stcs(&y1[n], r1);
    }
}

extern "C" void kernel_launch(void* const* d_in, const int* in_sizes, int n_in,
                              void* d_out, int out_size)
{
    const float* X = (const float*)d_in[0];   // [8192, 4096] fp32
    // d_in[1]: dense Hadamard matrix H — unused (FWHT).
    float* Y = (float*)d_out;

    const int rows = in_sizes[0] / HN;        // 8192
    fwht2_kernel<<<rows / 2, NTHREADS>>>(X, Y);
}

// round 15
// speedup vs baseline: 1.1603x; 1.1603x over previous
#include <cuda_runtime.h>

// Fast Walsh-Hadamard Transform, N=4096 fp32, one row per 256-thread CTA.
// All 12 stages in registers across 3 rounds:
//   round 1: bits {0,1,7,8}   lane-contiguous LDG.128, split 2+2 with the
//                             bit-0/1 stages interleaved under load latency
//   round 2: bits {2,3,4,5}   swizzled smem exchange
//   round 3: bits {6,9,10,11} swizzled smem exchange; coalesced scalar STG
// XOR swizzle on float4 slots: s' = s ^ ((s>>4)&7) — all four access
// patterns bank-conflict-free.  Output scaled by 2^-6 (normalized Hadamard).
//
// R15 (converged config): occ 6 / 40 regs (measured optimum across the
// occ{4,5,6,7,8} sweep), default loads (L2-friendly), __stcs stores
// (write-once output, evict-first), MLP_p1=2 load split (spread floor).

#define HN       4096
#define NTHREADS 256
#define RPT      16

__global__ __launch_bounds__(NTHREADS, 6)
void fwht_kernel(const float* __restrict__ X, float* __restrict__ Y)
{
    __shared__ float4 s4[HN / 4];              // 16 KB
    float* const sf = reinterpret_cast<float*>(s4);

    const size_t row = blockIdx.x;
    const float* __restrict__ x = X + row * HN;
    float*       __restrict__ y = Y + row * HN;

    const int t = threadIdx.x;
    const int w = t >> 5;          // warp 0..7
    const int l = t & 31;          // lane

    float v[RPT];

    // ---- Round 1: reg r = j*4+k -> n-bits r0,r1 = n0,n1 ; r2,r3 = n7,n8 ----
    // Split loads 2+2; bit-0/1 stages on each half run under the other pair's
    // latency (the halves only interact at the st=4/8 stages).
    {
        const float4* __restrict__ xv = reinterpret_cast<const float4*>(x);
        #pragma unroll
        for (int j = 0; j < 2; j++) {
            float4 a = xv[w * 128 + j * 32 + l];
            v[4*j+0] = a.x; v[4*j+1] = a.y; v[4*j+2] = a.z; v[4*j+3] = a.w;
        }
        #pragma unroll
        for (int st = 1; st <= 2; st <<= 1) {
            #pragma unroll
            for (int i = 0; i < 8; i++) {
                if (!(i & st)) {
                    float a = v[i], b = v[i ^ st];
                    v[i] = a + b;  v[i ^ st] = a - b;
                }
            }
        }
        #pragma unroll
        for (int j = 2; j < 4; j++) {
            float4 a = xv[w * 128 + j * 32 + l];
            v[4*j+0] = a.x; v[4*j+1] = a.y; v[4*j+2] = a.z; v[4*j+3] = a.w;
        }
        #pragma unroll
        for (int st = 1; st <= 2; st <<= 1) {
            #pragma unroll
            for (int i = 8; i < 16; i++) {
                if (!(i & st)) {
                    float a = v[i], b = v[i ^ st];
                    v[i] = a + b;  v[i ^ st] = a - b;
                }
            }
        }
        // stages st=4 (n7), st=8 (n8) across all regs
        #pragma unroll
        for (int st = 4; st < RPT; st <<= 1) {
            #pragma unroll
            for (int i = 0; i < RPT; i++) {
                if (!(i & st)) {
                    float a = v[i], b = v[i ^ st];
                    v[i] = a + b;  v[i ^ st] = a - b;
                }
            }
        }
    }

    // ---- Exchange 1 write: float4 slot s = w*128 + j*32 + l, swizzled ----
    #pragma unroll
    for (int j = 0; j < 4; j++) {
        int s  = w * 128 + j * 32 + l;
        int ss = s ^ ((s >> 4) & 7);
        s4[ss] = make_float4(v[4*j+0], v[4*j+1], v[4*j+2], v[4*j+3]);
    }
    __syncthreads();

    // ---- Round 2: thread fixes p=n0n1, q=n6, u=n7n8, w=n9..11; i = n2..5 ----
    const int p  = l & 3;
    const int q  = (l >> 2) & 1;
    const int u  = (l >> 3) & 3;
    const int sbase = 16 * q + 32 * u + 128 * w;   // slot base (i adds 0..15)
    const int sig   = q + 2 * u;                   // = ((s>>4)&7) for these slots
    #pragma unroll
    for (int i = 0; i < RPT; i++) {
        int ss = (sbase + i) ^ sig;
        v[i] = sf[ss * 4 + p];
    }
    #pragma unroll
    for (int st = 1; st < RPT; st <<= 1) {
        #pragma unroll
        for (int i = 0; i < RPT; i++) {
            if (!(i & st)) {
                float a = v[i], b = v[i ^ st];
                v[i] = a + b;  v[i ^ st] = a - b;
            }
        }
    }
    // write back to the same (thread-private) addresses — no barrier needed first
    #pragma unroll
    for (int i = 0; i < RPT; i++) {
        int ss = (sbase + i) ^ sig;
        sf[ss * 4 + p] = v[i];
    }
    __syncthreads();

    // ---- Round 3: thread fixes m = n0..5, u2 = n7n8 ; i2 -> {n6, n9..11} ----
    const int u2 = w >> 1;                 // n7,n8
    const int m  = ((w & 1) << 5) | l;     // n0..5
    const int mq = m >> 2;
    const int mp = m & 3;
    #pragma unroll
    for (int i2 = 0; i2 < RPT; i2++) {
        int b6 = i2 & 1, hi = i2 >> 1;
        int s  = mq + 16 * b6 + 32 * u2 + 128 * hi;
        int sg = b6 + 2 * u2;              // = ((s>>4)&7)
        v[i2] = sf[(s ^ sg) * 4 + mp];
    }
    #pragma unroll
    for (int st = 1; st < RPT; st <<= 1) {
        #pragma unroll
        for (int i = 0; i < RPT; i++) {
            if (!(i & st)) {
                float a = v[i], b = v[i ^ st];
                v[i] = a + b;  v[i ^ st] = a - b;
            }
        }
    }

    // ---- Store: n = m + 64*b6 + 128*u2 + 512*hi ; lanes contiguous 128B ----
    const int obase = m + 128 * u2;
    #pragma unroll
    for (int i2 = 0; i2 < RPT; i2++) {
        int b6 = i2 & 1, hi = i2 >> 1;
        __stcs(&y[obase + 64 * b6 + 512 * hi], v[i2] * 0.015625f);   // * 2^-6
    }
}

extern "C" void kernel_launch(void* const* d_in, const int* in_sizes, int n_in,
                              void* d_out, int out_size)
{
    const float* X = (const float*)d_in[0];   // [8192, 4096] fp32
    // d_in[1]: dense Hadamard matrix H — unused (FWHT).
    float* Y = (float*)d_out;

    const int rows = in_sizes[0] / HN;        // 8192
    fwht_kernel<<<rows, NTHREADS>>>(X, Y);
}